// round 3
// baseline (speedup 1.0000x reference)
#include <cuda_runtime.h>

#define BATCH 16
#define SEQ   2048
#define DIM   128

// ---------------------------------------------------------------------------
// K1: raw scores S[b,i,j] = sum_d Q[b,i,d] * K[b,j,d]
// 128x128 block tile, 256 threads, 8x8 per-thread register tile, BK=16.
// ---------------------------------------------------------------------------
__global__ __launch_bounds__(256) void scores_kernel(const float* __restrict__ Q,
                                                     const float* __restrict__ Km,
                                                     float* __restrict__ S) {
    const int b  = blockIdx.z;
    const int bm = blockIdx.y * 128;
    const int bn = blockIdx.x * 128;
    const float* Ab = Q  + (size_t)b * SEQ * DIM;
    const float* Bb = Km + (size_t)b * SEQ * DIM;
    float*       Cb = S  + (size_t)b * SEQ * SEQ;

    __shared__ float As[16][130];   // [k][m], padded (130: lc*130 % 32 spreads banks)
    __shared__ float Bs[16][130];   // [k][n]

    const int tid = threadIdx.x;
    const int lr  = tid >> 2;          // 0..63   load row
    const int lc  = (tid & 3) << 2;    // 0,4,8,12 load col (float4)
    const int tm  = (tid >> 4) << 3;   // 0..120
    const int tn  = (tid & 15) << 3;   // 0..120

    float acc[8][8];
    #pragma unroll
    for (int i = 0; i < 8; i++)
        #pragma unroll
        for (int j = 0; j < 8; j++) acc[i][j] = 0.0f;

    for (int kk = 0; kk < DIM; kk += 16) {
        #pragma unroll
        for (int h = 0; h < 2; h++) {
            const int r = lr + h * 64;
            float4 a4 = *(const float4*)(Ab + (size_t)(bm + r) * DIM + kk + lc);
            As[lc + 0][r] = a4.x; As[lc + 1][r] = a4.y;
            As[lc + 2][r] = a4.z; As[lc + 3][r] = a4.w;
            float4 b4 = *(const float4*)(Bb + (size_t)(bn + r) * DIM + kk + lc);
            Bs[lc + 0][r] = b4.x; Bs[lc + 1][r] = b4.y;
            Bs[lc + 2][r] = b4.z; Bs[lc + 3][r] = b4.w;
        }
        __syncthreads();
        #pragma unroll
        for (int p = 0; p < 16; p++) {
            float ra[8], rb[8];
            #pragma unroll
            for (int i = 0; i < 8; i++) ra[i] = As[p][tm + i];
            #pragma unroll
            for (int j = 0; j < 8; j++) rb[j] = Bs[p][tn + j];
            #pragma unroll
            for (int i = 0; i < 8; i++)
                #pragma unroll
                for (int j = 0; j < 8; j++)
                    acc[i][j] = fmaf(ra[i], rb[j], acc[i][j]);
        }
        __syncthreads();
    }

    #pragma unroll
    for (int i = 0; i < 8; i++) {
        float* crow = Cb + (size_t)(bm + tm + i) * SEQ + bn + tn;
        *(float4*)(crow)     = make_float4(acc[i][0], acc[i][1], acc[i][2], acc[i][3]);
        *(float4*)(crow + 4) = make_float4(acc[i][4], acc[i][5], acc[i][6], acc[i][7]);
    }
}

// ---------------------------------------------------------------------------
// K2: in-place row softmax over the last axis (2048). One CTA per row.
// ---------------------------------------------------------------------------
__global__ __launch_bounds__(256) void softmax_kernel(float* __restrict__ S) {
    float* row = S + (size_t)blockIdx.x * SEQ;
    const int tid = threadIdx.x;
    __shared__ float red[16];

    float4* r4 = (float4*)row;
    const int NV = SEQ / 4;   // 512

    // --- row max ---
    float m = -1e30f;
    #pragma unroll
    for (int j = tid; j < NV; j += 256) {
        float4 v = r4[j];
        m = fmaxf(m, fmaxf(fmaxf(v.x, v.y), fmaxf(v.z, v.w)));
    }
    #pragma unroll
    for (int o = 16; o > 0; o >>= 1) m = fmaxf(m, __shfl_xor_sync(0xffffffffu, m, o));
    if ((tid & 31) == 0) red[tid >> 5] = m;
    __syncthreads();
    float mrow = red[0];
    #pragma unroll
    for (int w = 1; w < 8; w++) mrow = fmaxf(mrow, red[w]);

    // --- row sum of exp ---
    float s = 0.0f;
    #pragma unroll
    for (int j = tid; j < NV; j += 256) {
        float4 v = r4[j];
        s += __expf(v.x - mrow) + __expf(v.y - mrow) +
             __expf(v.z - mrow) + __expf(v.w - mrow);
    }
    #pragma unroll
    for (int o = 16; o > 0; o >>= 1) s += __shfl_xor_sync(0xffffffffu, s, o);
    if ((tid & 31) == 0) red[8 + (tid >> 5)] = s;
    __syncthreads();
    float srow = 0.0f;
    #pragma unroll
    for (int w = 0; w < 8; w++) srow += red[8 + w];
    const float inv = 1.0f / srow;

    // --- normalize & write back ---
    #pragma unroll
    for (int j = tid; j < NV; j += 256) {
        float4 v = r4[j];
        v.x = __expf(v.x - mrow) * inv;
        v.y = __expf(v.y - mrow) * inv;
        v.z = __expf(v.z - mrow) * inv;
        v.w = __expf(v.w - mrow) * inv;
        r4[j] = v;
    }
}

// ---------------------------------------------------------------------------
// K3: O[b,i,d] = sum_j P[b,i,j] * V[b,j,d]
// 64x128 block tile, 256 threads, 4x8 per-thread register tile, BK=16.
// ---------------------------------------------------------------------------
__global__ __launch_bounds__(256) void av_kernel(const float* __restrict__ P,
                                                 const float* __restrict__ Vm,
                                                 float* __restrict__ O) {
    const int b  = blockIdx.z;
    const int bm = blockIdx.y * 64;
    const float* Ab = P  + (size_t)b * SEQ * SEQ;
    const float* Bb = Vm + (size_t)b * SEQ * DIM;
    float*       Cb = O  + (size_t)b * SEQ * DIM;

    __shared__ float As[16][66];    // [k][m], padded (66: lc*66 % 32 spreads banks)
    __shared__ float Bs[16][128];   // [k][n] natural

    const int tid = threadIdx.x;
    const int lr  = tid >> 2;          // 0..63
    const int lc  = (tid & 3) << 2;    // 0,4,8,12
    const int br  = tid >> 5;          // 0..7
    const int bc  = (tid & 31) << 2;   // 0..124
    const int tm  = (tid >> 4) << 2;   // 0..60
    const int tn  = (tid & 15) << 3;   // 0..120

    float acc[4][8];
    #pragma unroll
    for (int i = 0; i < 4; i++)
        #pragma unroll
        for (int j = 0; j < 8; j++) acc[i][j] = 0.0f;

    for (int kk = 0; kk < SEQ; kk += 16) {
        float4 a4 = *(const float4*)(Ab + (size_t)(bm + lr) * SEQ + kk + lc);
        As[lc + 0][lr] = a4.x; As[lc + 1][lr] = a4.y;
        As[lc + 2][lr] = a4.z; As[lc + 3][lr] = a4.w;
        #pragma unroll
        for (int h = 0; h < 2; h++) {
            const int r = br + h * 8;
            float4 b4 = *(const float4*)(Bb + (size_t)(kk + r) * DIM + bc);
            *(float4*)(&Bs[r][bc]) = b4;
        }
        __syncthreads();
        #pragma unroll
        for (int p = 0; p < 16; p++) {
            float ra[4], rb[8];
            #pragma unroll
            for (int i = 0; i < 4; i++) ra[i] = As[p][tm + i];
            #pragma unroll
            for (int j = 0; j < 8; j++) rb[j] = Bs[p][tn + j];
            #pragma unroll
            for (int i = 0; i < 4; i++)
                #pragma unroll
                for (int j = 0; j < 8; j++)
                    acc[i][j] = fmaf(ra[i], rb[j], acc[i][j]);
        }
        __syncthreads();
    }

    #pragma unroll
    for (int i = 0; i < 4; i++) {
        float* crow = Cb + (size_t)(bm + tm + i) * DIM + tn;
        *(float4*)(crow)     = make_float4(acc[i][0], acc[i][1], acc[i][2], acc[i][3]);
        *(float4*)(crow + 4) = make_float4(acc[i][4], acc[i][5], acc[i][6], acc[i][7]);
    }
}

// ---------------------------------------------------------------------------
// Launch: out = [ output (B*N*D) | attn (B*N*N) ]  (tuple order)
// ---------------------------------------------------------------------------
extern "C" void kernel_launch(void* const* d_in, const int* in_sizes, int n_in,
                              void* d_out, int out_size) {
    const float* q = (const float*)d_in[0];
    const float* k = (const float*)d_in[1];
    const float* v = (const float*)d_in[2];
    float* out  = (float*)d_out;
    float* attn = out + (size_t)BATCH * SEQ * DIM;

    dim3 g1(SEQ / 128, SEQ / 128, BATCH);   // 16 x 16 x 16 = 4096 CTAs
    scores_kernel<<<g1, 256>>>(q, k, attn);

    softmax_kernel<<<BATCH * SEQ, 256>>>(attn);

    dim3 g3(1, SEQ / 64, BATCH);            // 512 CTAs
    av_kernel<<<g3, 256>>>(attn, v, out);
}

// round 6
// speedup vs baseline: 1.9647x; 1.9647x over previous
#include <cuda_runtime.h>
#include <cuda_bf16.h>
#include <cstdint>

#define BATCH 16
#define SEQ   2048
#define DIM   128

// ---------------------------------------------------------------------------
// Static device scratch: split bf16 copies of Q, K and transposed V (~50 MB).
// ---------------------------------------------------------------------------
static __device__ __align__(1024) __nv_bfloat16 g_qh[BATCH * SEQ * DIM];
static __device__ __align__(1024) __nv_bfloat16 g_ql[BATCH * SEQ * DIM];
static __device__ __align__(1024) __nv_bfloat16 g_kh[BATCH * SEQ * DIM];
static __device__ __align__(1024) __nv_bfloat16 g_kl[BATCH * SEQ * DIM];
static __device__ __align__(1024) __nv_bfloat16 g_vth[BATCH * DIM * SEQ]; // [b][d][n]
static __device__ __align__(1024) __nv_bfloat16 g_vtl[BATCH * DIM * SEQ];

// ---------------------------------------------------------------------------
// Helpers (baseline PTX only: ldmatrix / mma.sync / cp.async — no tcgen05)
// ---------------------------------------------------------------------------
__device__ __forceinline__ uint32_t smem_u32(const void* p) {
    uint32_t a;
    asm("{ .reg .u64 t; cvta.to.shared.u64 t, %1; cvt.u32.u64 %0, t; }"
        : "=r"(a) : "l"(p));
    return a;
}

#define CP_ASYNC16(dst_u32, src_ptr) \
    asm volatile("cp.async.cg.shared.global [%0], [%1], 16;" \
                 :: "r"(dst_u32), "l"(src_ptr))
#define CP_ASYNC_WAIT_ALL() \
    asm volatile("cp.async.commit_group;\ncp.async.wait_group 0;" ::: "memory")

__device__ __forceinline__ void ldmx4(uint32_t* r, uint32_t addr) {
    asm volatile("ldmatrix.sync.aligned.m8n8.x4.shared.b16 {%0,%1,%2,%3}, [%4];"
                 : "=r"(r[0]), "=r"(r[1]), "=r"(r[2]), "=r"(r[3]) : "r"(addr));
}

__device__ __forceinline__ void mma16816(float* c, const uint32_t* a,
                                         const uint32_t* b) {
    asm volatile(
        "mma.sync.aligned.m16n8k16.row.col.f32.bf16.bf16.f32 "
        "{%0,%1,%2,%3}, {%4,%5,%6,%7}, {%8,%9}, {%0,%1,%2,%3};"
        : "+f"(c[0]), "+f"(c[1]), "+f"(c[2]), "+f"(c[3])
        : "r"(a[0]), "r"(a[1]), "r"(a[2]), "r"(a[3]), "r"(b[0]), "r"(b[1]));
}

// fp32 -> (bf16 hi, bf16 lo) split, two values packed per uint32
__device__ __forceinline__ void split2(float a, float b, uint32_t& h, uint32_t& l) {
    __nv_bfloat16 ha = __float2bfloat16_rn(a);
    __nv_bfloat16 hb = __float2bfloat16_rn(b);
    __nv_bfloat16 la = __float2bfloat16_rn(a - __bfloat162float(ha));
    __nv_bfloat16 lb = __float2bfloat16_rn(b - __bfloat162float(hb));
    h = (uint32_t)__bfloat16_as_ushort(ha) | ((uint32_t)__bfloat16_as_ushort(hb) << 16);
    l = (uint32_t)__bfloat16_as_ushort(la) | ((uint32_t)__bfloat16_as_ushort(lb) << 16);
}

// ---------------------------------------------------------------------------
// K0a: elementwise split fp32 -> (hi, lo) bf16 (ISK: 0 = Q, 1 = K)
// ---------------------------------------------------------------------------
template <int ISK>
__global__ __launch_bounds__(256) void split_kernel(const float* __restrict__ src,
                                                    int n4) {
    int i = blockIdx.x * 256 + threadIdx.x;
    if (i >= n4) return;
    __nv_bfloat16* dh = ISK ? g_kh : g_qh;
    __nv_bfloat16* dl = ISK ? g_kl : g_ql;
    float4 x = ((const float4*)src)[i];
    uint32_t h0, l0, h1, l1;
    split2(x.x, x.y, h0, l0);
    split2(x.z, x.w, h1, l1);
    ((uint2*)dh)[i] = make_uint2(h0, h1);
    ((uint2*)dl)[i] = make_uint2(l0, l1);
}

// ---------------------------------------------------------------------------
// K0b: V transpose + split: vt[b][d][n] = v[b][n][d] (hi/lo bf16)
// ---------------------------------------------------------------------------
__global__ __launch_bounds__(256) void vtrans_kernel(const float* __restrict__ V) {
    __shared__ float tile[32][33];
    const int b  = blockIdx.z;
    const int n0 = blockIdx.x * 32;
    const int d0 = blockIdx.y * 32;
    const int tx = threadIdx.x & 31;
    const int ty = threadIdx.x >> 5;   // 0..7
    #pragma unroll
    for (int r = 0; r < 4; r++)
        tile[ty + 8 * r][tx] = V[((size_t)b * SEQ + n0 + ty + 8 * r) * DIM + d0 + tx];
    __syncthreads();
    #pragma unroll
    for (int r = 0; r < 4; r++) {
        int d = d0 + ty + 8 * r;
        float x = tile[tx][ty + 8 * r];
        __nv_bfloat16 h = __float2bfloat16_rn(x);
        __nv_bfloat16 l = __float2bfloat16_rn(x - __bfloat162float(h));
        size_t idx = ((size_t)b * DIM + d) * SEQ + n0 + tx;
        g_vth[idx] = h;
        g_vtl[idx] = l;
    }
}

// ---------------------------------------------------------------------------
// K1: scores S = Q K^T via mma.sync bf16, 3-pass split (hh + hl + lh).
// CTA: 128x128 tile, 8 warps (4x2), warp tile 32x64, K-chunks of 64.
// smem rows: 64 bf16 = 128 B = 8 chunks of 16 B, chunk xor-swizzled by row&7.
// ---------------------------------------------------------------------------
#define SQH 0
#define SQL 16384
#define SKH 32768
#define SKL 49152
#define SC_BYTES 65536

__global__ __launch_bounds__(256, 2) void scores_mma_kernel(float* __restrict__ S) {
    extern __shared__ char smem[];
    const uint32_t sb = smem_u32(smem);
    const int tid  = threadIdx.x;
    const int lane = tid & 31;
    const int wid  = tid >> 5;
    const int b  = blockIdx.z;
    const int bm = blockIdx.y * 128;
    const int bn = blockIdx.x * 128;
    const int wm = (wid >> 1) * 32;
    const int wn = (wid & 1) * 64;

    float c[2][8][4];
    #pragma unroll
    for (int i = 0; i < 2; i++)
        #pragma unroll
        for (int j = 0; j < 8; j++)
            #pragma unroll
            for (int q = 0; q < 4; q++) c[i][j][q] = 0.0f;

    // loader mapping: thread -> (row, 4 chunks)
    const int lr  = tid >> 1;             // 0..127
    const int lc0 = (tid & 1) * 4;        // 0 or 4
    const int lsw = lr & 7;
    const size_t qbase = ((size_t)b * SEQ + bm + lr) * DIM;
    const size_t kbase = ((size_t)b * SEQ + bn + lr) * DIM;

    // ldmatrix mapping
    const int s7 = lane & 7;
    const uint32_t a_row = (uint32_t)(wm + (lane & 15)) * 128;
    const int a_k = (lane >> 4) & 1;
    const uint32_t b_row = (uint32_t)(wn + (lane & 7) + ((lane >> 4) << 3)) * 128;
    const int b_k = (lane >> 3) & 1;

    for (int kc = 0; kc < 2; kc++) {
        const int kk = kc * 64;
        #pragma unroll
        for (int j = 0; j < 4; j++) {
            const int ch = lc0 + j;
            const uint32_t doff = lr * 128 + (uint32_t)((ch ^ lsw) << 4);
            CP_ASYNC16(sb + SQH + doff, g_qh + qbase + kk + ch * 8);
            CP_ASYNC16(sb + SQL + doff, g_ql + qbase + kk + ch * 8);
            CP_ASYNC16(sb + SKH + doff, g_kh + kbase + kk + ch * 8);
            CP_ASYNC16(sb + SKL + doff, g_kl + kbase + kk + ch * 8);
        }
        CP_ASYNC_WAIT_ALL();
        __syncthreads();

        #pragma unroll
        for (int pass = 0; pass < 3; pass++) {
            const uint32_t Ab = sb + (pass == 2 ? SQL : SQH);
            const uint32_t Bb = sb + (pass == 1 ? SKL : SKH);
            #pragma unroll
            for (int ks = 0; ks < 4; ks++) {
                uint32_t a[2][4], bf[4][4];
                const uint32_t ac = (uint32_t)(((2 * ks + a_k) ^ s7) << 4);
                ldmx4(a[0], Ab + a_row + ac);
                ldmx4(a[1], Ab + a_row + 2048 + ac);
                const uint32_t bc = (uint32_t)(((2 * ks + b_k) ^ s7) << 4);
                #pragma unroll
                for (int nt = 0; nt < 4; nt++)
                    ldmx4(bf[nt], Bb + b_row + nt * 2048 + bc);
                #pragma unroll
                for (int mt = 0; mt < 2; mt++)
                    #pragma unroll
                    for (int nb = 0; nb < 8; nb++)
                        mma16816(c[mt][nb], a[mt], &bf[nb >> 1][(nb & 1) * 2]);
            }
        }
        __syncthreads();
    }

    // epilogue: C-fragment -> global
    const int g = lane >> 2, t = lane & 3;
    #pragma unroll
    for (int mt = 0; mt < 2; mt++) {
        const size_t r0 = (size_t)b * SEQ + bm + wm + mt * 16 + g;
        #pragma unroll
        for (int nb = 0; nb < 8; nb++) {
            const int col = bn + wn + nb * 8 + 2 * t;
            *(float2*)&S[r0 * SEQ + col]       = make_float2(c[mt][nb][0], c[mt][nb][1]);
            *(float2*)&S[(r0 + 8) * SEQ + col] = make_float2(c[mt][nb][2], c[mt][nb][3]);
        }
    }
}

// ---------------------------------------------------------------------------
// K2: in-place row softmax (proven baseline)
// ---------------------------------------------------------------------------
__global__ __launch_bounds__(256) void softmax_kernel(float* __restrict__ S) {
    float* row = S + (size_t)blockIdx.x * SEQ;
    const int tid = threadIdx.x;
    __shared__ float red[16];
    float4* r4 = (float4*)row;
    const int NV = SEQ / 4;

    float m = -1e30f;
    for (int j = tid; j < NV; j += 256) {
        float4 v = r4[j];
        m = fmaxf(m, fmaxf(fmaxf(v.x, v.y), fmaxf(v.z, v.w)));
    }
    #pragma unroll
    for (int o = 16; o > 0; o >>= 1) m = fmaxf(m, __shfl_xor_sync(0xffffffffu, m, o));
    if ((tid & 31) == 0) red[tid >> 5] = m;
    __syncthreads();
    float mrow = red[0];
    #pragma unroll
    for (int w = 1; w < 8; w++) mrow = fmaxf(mrow, red[w]);

    float s = 0.0f;
    for (int j = tid; j < NV; j += 256) {
        float4 v = r4[j];
        s += __expf(v.x - mrow) + __expf(v.y - mrow) +
             __expf(v.z - mrow) + __expf(v.w - mrow);
    }
    #pragma unroll
    for (int o = 16; o > 0; o >>= 1) s += __shfl_xor_sync(0xffffffffu, s, o);
    if ((tid & 31) == 0) red[8 + (tid >> 5)] = s;
    __syncthreads();
    float srow = 0.0f;
    #pragma unroll
    for (int w = 0; w < 8; w++) srow += red[8 + w];
    const float inv = 1.0f / srow;

    for (int j = tid; j < NV; j += 256) {
        float4 v = r4[j];
        v.x = __expf(v.x - mrow) * inv;
        v.y = __expf(v.y - mrow) * inv;
        v.z = __expf(v.z - mrow) * inv;
        v.w = __expf(v.w - mrow) * inv;
        r4[j] = v;
    }
}

// ---------------------------------------------------------------------------
// K3: O = P @ V via mma.sync bf16, 3-pass split. P split to hi/lo in-kernel;
// V pre-transposed ([b][d][n]) so both operands are K-contiguous.
// CTA: 128(m) x 128(d), K = 2048 in 32 chunks of 64.
// ---------------------------------------------------------------------------
#define AAH 0
#define AAL 16384
#define ABH 32768
#define ABL 49152
#define AV_BYTES 65536

__global__ __launch_bounds__(256, 2) void av_mma_kernel(const float* __restrict__ P,
                                                        float* __restrict__ O) {
    extern __shared__ char smem[];
    const uint32_t sb = smem_u32(smem);
    const int tid  = threadIdx.x;
    const int lane = tid & 31;
    const int wid  = tid >> 5;
    const int bm = blockIdx.x * 128;
    const int b  = blockIdx.y;
    const int wm = (wid >> 1) * 32;
    const int wn = (wid & 1) * 64;

    float c[2][8][4];
    #pragma unroll
    for (int i = 0; i < 2; i++)
        #pragma unroll
        for (int j = 0; j < 8; j++)
            #pragma unroll
            for (int q = 0; q < 4; q++) c[i][j][q] = 0.0f;

    const int lr  = tid >> 1;
    const int lc0 = (tid & 1) * 4;
    const int lsw = lr & 7;
    const float* prow = P + ((size_t)b * SEQ + bm + lr) * SEQ + (tid & 1) * 32;
    const size_t vbase = ((size_t)b * DIM + lr) * SEQ;

    const int s7 = lane & 7;
    const uint32_t a_row = (uint32_t)(wm + (lane & 15)) * 128;
    const int a_k = (lane >> 4) & 1;
    const uint32_t b_row = (uint32_t)(wn + (lane & 7) + ((lane >> 4) << 3)) * 128;
    const int b_k = (lane >> 3) & 1;

    for (int kc = 0; kc < 32; kc++) {
        const int kk = kc * 64;

        // B: V hi/lo rows via cp.async (issue first so it overlaps the split)
        #pragma unroll
        for (int j = 0; j < 4; j++) {
            const int ch = lc0 + j;
            const uint32_t doff = lr * 128 + (uint32_t)((ch ^ lsw) << 4);
            CP_ASYNC16(sb + ABH + doff, g_vth + vbase + kk + ch * 8);
            CP_ASYNC16(sb + ABL + doff, g_vtl + vbase + kk + ch * 8);
        }

        // A: 32 fp32 of own P row -> split -> swizzled STS
        {
            const float4* src = (const float4*)(prow + kk);
            #pragma unroll
            for (int j = 0; j < 4; j++) {
                float4 x0 = src[2 * j], x1 = src[2 * j + 1];
                uint4 hv, lv;
                split2(x0.x, x0.y, hv.x, lv.x);
                split2(x0.z, x0.w, hv.y, lv.y);
                split2(x1.x, x1.y, hv.z, lv.z);
                split2(x1.z, x1.w, hv.w, lv.w);
                const uint32_t doff = lr * 128 + (uint32_t)((((lc0 + j)) ^ lsw) << 4);
                *(uint4*)(smem + AAH + doff) = hv;
                *(uint4*)(smem + AAL + doff) = lv;
            }
        }
        CP_ASYNC_WAIT_ALL();
        __syncthreads();

        #pragma unroll
        for (int pass = 0; pass < 3; pass++) {
            const uint32_t Ab = sb + (pass == 2 ? AAL : AAH);
            const uint32_t Bb = sb + (pass == 1 ? ABL : ABH);
            #pragma unroll
            for (int ks = 0; ks < 4; ks++) {
                uint32_t a[2][4], bf[4][4];
                const uint32_t ac = (uint32_t)(((2 * ks + a_k) ^ s7) << 4);
                ldmx4(a[0], Ab + a_row + ac);
                ldmx4(a[1], Ab + a_row + 2048 + ac);
                const uint32_t bc = (uint32_t)(((2 * ks + b_k) ^ s7) << 4);
                #pragma unroll
                for (int nt = 0; nt < 4; nt++)
                    ldmx4(bf[nt], Bb + b_row + nt * 2048 + bc);
                #pragma unroll
                for (int mt = 0; mt < 2; mt++)
                    #pragma unroll
                    for (int nb = 0; nb < 8; nb++)
                        mma16816(c[mt][nb], a[mt], &bf[nb >> 1][(nb & 1) * 2]);
            }
        }
        __syncthreads();
    }

    const int g = lane >> 2, t = lane & 3;
    #pragma unroll
    for (int mt = 0; mt < 2; mt++) {
        const size_t r0 = (size_t)b * SEQ + bm + wm + mt * 16 + g;
        #pragma unroll
        for (int nb = 0; nb < 8; nb++) {
            const int col = wn + nb * 8 + 2 * t;
            *(float2*)&O[r0 * DIM + col]       = make_float2(c[mt][nb][0], c[mt][nb][1]);
            *(float2*)&O[(r0 + 8) * DIM + col] = make_float2(c[mt][nb][2], c[mt][nb][3]);
        }
    }
}

// ---------------------------------------------------------------------------
// Launch: out = [ output (B*N*D) | attn (B*N*N) ]
// ---------------------------------------------------------------------------
extern "C" void kernel_launch(void* const* d_in, const int* in_sizes, int n_in,
                              void* d_out, int out_size) {
    const float* q = (const float*)d_in[0];
    const float* k = (const float*)d_in[1];
    const float* v = (const float*)d_in[2];
    float* out  = (float*)d_out;
    float* attn = out + (size_t)BATCH * SEQ * DIM;

    cudaFuncSetAttribute(scores_mma_kernel,
                         cudaFuncAttributeMaxDynamicSharedMemorySize, SC_BYTES);
    cudaFuncSetAttribute(av_mma_kernel,
                         cudaFuncAttributeMaxDynamicSharedMemorySize, AV_BYTES);

    const int n4 = BATCH * SEQ * DIM / 4;
    split_kernel<0><<<(n4 + 255) / 256, 256>>>(q, n4);
    split_kernel<1><<<(n4 + 255) / 256, 256>>>(k, n4);

    dim3 gv(SEQ / 32, DIM / 32, BATCH);
    vtrans_kernel<<<gv, 256>>>(v);

    dim3 g1(SEQ / 128, SEQ / 128, BATCH);
    scores_mma_kernel<<<g1, 256, SC_BYTES>>>(attn);

    softmax_kernel<<<BATCH * SEQ, 256>>>(attn);

    dim3 g3(SEQ / 128, BATCH);
    av_mma_kernel<<<g3, 256, AV_BYTES>>>(attn, out);
}

// round 7
// speedup vs baseline: 2.4652x; 1.2547x over previous
#include <cuda_runtime.h>
#include <cuda_bf16.h>
#include <cuda_fp16.h>
#include <cstdint>

#define BATCH 16
#define SEQ   2048
#define DIM   128
#define PSCALE   16384.0f
#define PSCALE_I 6.103515625e-05f   // 1/16384

// ---------------------------------------------------------------------------
// Static device scratch: split bf16 Q/K, fp16 transposed V (~42 MB).
// ---------------------------------------------------------------------------
static __device__ __align__(1024) __nv_bfloat16 g_qh[BATCH * SEQ * DIM];
static __device__ __align__(1024) __nv_bfloat16 g_ql[BATCH * SEQ * DIM];
static __device__ __align__(1024) __nv_bfloat16 g_kh[BATCH * SEQ * DIM];
static __device__ __align__(1024) __nv_bfloat16 g_kl[BATCH * SEQ * DIM];
static __device__ __align__(1024) __half        g_vh[BATCH * DIM * SEQ]; // [b][d][n]

// ---------------------------------------------------------------------------
// Helpers (baseline PTX only: ldmatrix / mma.sync / cp.async)
// ---------------------------------------------------------------------------
__device__ __forceinline__ uint32_t smem_u32(const void* p) {
    uint32_t a;
    asm("{ .reg .u64 t; cvta.to.shared.u64 t, %1; cvt.u32.u64 %0, t; }"
        : "=r"(a) : "l"(p));
    return a;
}

#define CP_ASYNC16(dst_u32, src_ptr) \
    asm volatile("cp.async.cg.shared.global [%0], [%1], 16;" \
                 :: "r"(dst_u32), "l"(src_ptr))
#define CP_COMMIT()  asm volatile("cp.async.commit_group;" ::: "memory")
#define CP_WAIT0()   asm volatile("cp.async.wait_group 0;" ::: "memory")
#define CP_ASYNC_WAIT_ALL() \
    asm volatile("cp.async.commit_group;\ncp.async.wait_group 0;" ::: "memory")

__device__ __forceinline__ void ldmx4(uint32_t* r, uint32_t addr) {
    asm volatile("ldmatrix.sync.aligned.m8n8.x4.shared.b16 {%0,%1,%2,%3}, [%4];"
                 : "=r"(r[0]), "=r"(r[1]), "=r"(r[2]), "=r"(r[3]) : "r"(addr));
}

__device__ __forceinline__ void mma16816_bf(float* c, const uint32_t* a,
                                            const uint32_t* b) {
    asm volatile(
        "mma.sync.aligned.m16n8k16.row.col.f32.bf16.bf16.f32 "
        "{%0,%1,%2,%3}, {%4,%5,%6,%7}, {%8,%9}, {%0,%1,%2,%3};"
        : "+f"(c[0]), "+f"(c[1]), "+f"(c[2]), "+f"(c[3])
        : "r"(a[0]), "r"(a[1]), "r"(a[2]), "r"(a[3]), "r"(b[0]), "r"(b[1]));
}

__device__ __forceinline__ void mma16816_fp(float* c, const uint32_t* a,
                                            const uint32_t* b) {
    asm volatile(
        "mma.sync.aligned.m16n8k16.row.col.f32.f16.f16.f32 "
        "{%0,%1,%2,%3}, {%4,%5,%6,%7}, {%8,%9}, {%0,%1,%2,%3};"
        : "+f"(c[0]), "+f"(c[1]), "+f"(c[2]), "+f"(c[3])
        : "r"(a[0]), "r"(a[1]), "r"(a[2]), "r"(a[3]), "r"(b[0]), "r"(b[1]));
}

// fp32 -> (bf16 hi, bf16 lo), two values packed per uint32
__device__ __forceinline__ void split2(float a, float b, uint32_t& h, uint32_t& l) {
    __nv_bfloat16 ha = __float2bfloat16_rn(a);
    __nv_bfloat16 hb = __float2bfloat16_rn(b);
    __nv_bfloat16 la = __float2bfloat16_rn(a - __bfloat162float(ha));
    __nv_bfloat16 lb = __float2bfloat16_rn(b - __bfloat162float(hb));
    h = (uint32_t)__bfloat16_as_ushort(ha) | ((uint32_t)__bfloat16_as_ushort(hb) << 16);
    l = (uint32_t)__bfloat16_as_ushort(la) | ((uint32_t)__bfloat16_as_ushort(lb) << 16);
}

// fp32 -> (fp16 hi, fp16 lo), two values packed per uint32
__device__ __forceinline__ void split2h(float a, float b, uint32_t& h, uint32_t& l) {
    __half ha = __float2half_rn(a);
    __half hb = __float2half_rn(b);
    __half la = __float2half_rn(a - __half2float(ha));
    __half lb = __float2half_rn(b - __half2float(hb));
    h = (uint32_t)__half_as_ushort(ha) | ((uint32_t)__half_as_ushort(hb) << 16);
    l = (uint32_t)__half_as_ushort(la) | ((uint32_t)__half_as_ushort(lb) << 16);
}

// ---------------------------------------------------------------------------
// K0a: elementwise split fp32 -> (hi, lo) bf16 (ISK: 0 = Q, 1 = K)
// ---------------------------------------------------------------------------
template <int ISK>
__global__ __launch_bounds__(256) void split_kernel(const float* __restrict__ src,
                                                    int n4) {
    int i = blockIdx.x * 256 + threadIdx.x;
    if (i >= n4) return;
    __nv_bfloat16* dh = ISK ? g_kh : g_qh;
    __nv_bfloat16* dl = ISK ? g_kl : g_ql;
    float4 x = ((const float4*)src)[i];
    uint32_t h0, l0, h1, l1;
    split2(x.x, x.y, h0, l0);
    split2(x.z, x.w, h1, l1);
    ((uint2*)dh)[i] = make_uint2(h0, h1);
    ((uint2*)dl)[i] = make_uint2(l0, l1);
}

// ---------------------------------------------------------------------------
// K0b: V transpose to fp16: vh[b][d][n] = fp16(v[b][n][d])
// ---------------------------------------------------------------------------
__global__ __launch_bounds__(256) void vtrans_kernel(const float* __restrict__ V) {
    __shared__ float tile[32][33];
    const int b  = blockIdx.z;
    const int n0 = blockIdx.x * 32;
    const int d0 = blockIdx.y * 32;
    const int tx = threadIdx.x & 31;
    const int ty = threadIdx.x >> 5;   // 0..7
    #pragma unroll
    for (int r = 0; r < 4; r++)
        tile[ty + 8 * r][tx] = V[((size_t)b * SEQ + n0 + ty + 8 * r) * DIM + d0 + tx];
    __syncthreads();
    #pragma unroll
    for (int r = 0; r < 4; r++) {
        int d = d0 + ty + 8 * r;
        float x = tile[tx][ty + 8 * r];
        g_vh[((size_t)b * DIM + d) * SEQ + n0 + tx] = __float2half_rn(x);
    }
}

// ---------------------------------------------------------------------------
// K1: scores S = Q K^T via mma.sync bf16, 3-pass split (hh + hl + lh).
// (unchanged from passing R6 kernel)
// ---------------------------------------------------------------------------
#define SQH 0
#define SQL 16384
#define SKH 32768
#define SKL 49152
#define SC_BYTES 65536

__global__ __launch_bounds__(256, 2) void scores_mma_kernel(float* __restrict__ S) {
    extern __shared__ char smem[];
    const uint32_t sb = smem_u32(smem);
    const int tid  = threadIdx.x;
    const int lane = tid & 31;
    const int wid  = tid >> 5;
    const int b  = blockIdx.z;
    const int bm = blockIdx.y * 128;
    const int bn = blockIdx.x * 128;
    const int wm = (wid >> 1) * 32;
    const int wn = (wid & 1) * 64;

    float c[2][8][4];
    #pragma unroll
    for (int i = 0; i < 2; i++)
        #pragma unroll
        for (int j = 0; j < 8; j++)
            #pragma unroll
            for (int q = 0; q < 4; q++) c[i][j][q] = 0.0f;

    const int lr  = tid >> 1;
    const int lc0 = (tid & 1) * 4;
    const int lsw = lr & 7;
    const size_t qbase = ((size_t)b * SEQ + bm + lr) * DIM;
    const size_t kbase = ((size_t)b * SEQ + bn + lr) * DIM;

    const int s7 = lane & 7;
    const uint32_t a_row = (uint32_t)(wm + (lane & 15)) * 128;
    const int a_k = (lane >> 4) & 1;
    const uint32_t b_row = (uint32_t)(wn + (lane & 7) + ((lane >> 4) << 3)) * 128;
    const int b_k = (lane >> 3) & 1;

    for (int kc = 0; kc < 2; kc++) {
        const int kk = kc * 64;
        #pragma unroll
        for (int j = 0; j < 4; j++) {
            const int ch = lc0 + j;
            const uint32_t doff = lr * 128 + (uint32_t)((ch ^ lsw) << 4);
            CP_ASYNC16(sb + SQH + doff, g_qh + qbase + kk + ch * 8);
            CP_ASYNC16(sb + SQL + doff, g_ql + qbase + kk + ch * 8);
            CP_ASYNC16(sb + SKH + doff, g_kh + kbase + kk + ch * 8);
            CP_ASYNC16(sb + SKL + doff, g_kl + kbase + kk + ch * 8);
        }
        CP_ASYNC_WAIT_ALL();
        __syncthreads();

        #pragma unroll
        for (int pass = 0; pass < 3; pass++) {
            const uint32_t Ab = sb + (pass == 2 ? SQL : SQH);
            const uint32_t Bb = sb + (pass == 1 ? SKL : SKH);
            #pragma unroll
            for (int ks = 0; ks < 4; ks++) {
                uint32_t a[2][4], bf[4][4];
                const uint32_t ac = (uint32_t)(((2 * ks + a_k) ^ s7) << 4);
                ldmx4(a[0], Ab + a_row + ac);
                ldmx4(a[1], Ab + a_row + 2048 + ac);
                const uint32_t bc = (uint32_t)(((2 * ks + b_k) ^ s7) << 4);
                #pragma unroll
                for (int nt = 0; nt < 4; nt++)
                    ldmx4(bf[nt], Bb + b_row + nt * 2048 + bc);
                #pragma unroll
                for (int mt = 0; mt < 2; mt++)
                    #pragma unroll
                    for (int nb = 0; nb < 8; nb++)
                        mma16816_bf(c[mt][nb], a[mt], &bf[nb >> 1][(nb & 1) * 2]);
            }
        }
        __syncthreads();
    }

    const int g = lane >> 2, t = lane & 3;
    #pragma unroll
    for (int mt = 0; mt < 2; mt++) {
        const size_t r0 = (size_t)b * SEQ + bm + wm + mt * 16 + g;
        #pragma unroll
        for (int nb = 0; nb < 8; nb++) {
            const int col = bn + wn + nb * 8 + 2 * t;
            *(float2*)&S[r0 * SEQ + col]       = make_float2(c[mt][nb][0], c[mt][nb][1]);
            *(float2*)&S[(r0 + 8) * SEQ + col] = make_float2(c[mt][nb][2], c[mt][nb][3]);
        }
    }
}

// ---------------------------------------------------------------------------
// K2: in-place row softmax, smem-cached row (single global read, single exp)
// ---------------------------------------------------------------------------
__global__ __launch_bounds__(256) void softmax_kernel(float* __restrict__ S) {
    __shared__ float buf[SEQ];
    __shared__ float red[16];
    float* row = S + (size_t)blockIdx.x * SEQ;
    const int tid = threadIdx.x;
    float4* r4 = (float4*)row;
    float4* b4 = (float4*)buf;
    const int NV = SEQ / 4;   // 512

    float m = -1e30f;
    #pragma unroll
    for (int j = tid; j < NV; j += 256) {
        float4 v = r4[j];
        b4[j] = v;
        m = fmaxf(m, fmaxf(fmaxf(v.x, v.y), fmaxf(v.z, v.w)));
    }
    #pragma unroll
    for (int o = 16; o > 0; o >>= 1) m = fmaxf(m, __shfl_xor_sync(0xffffffffu, m, o));
    if ((tid & 31) == 0) red[tid >> 5] = m;
    __syncthreads();
    float mrow = red[0];
    #pragma unroll
    for (int w = 1; w < 8; w++) mrow = fmaxf(mrow, red[w]);

    float s = 0.0f;
    #pragma unroll
    for (int j = tid; j < NV; j += 256) {
        float4 v = b4[j];
        v.x = __expf(v.x - mrow);
        v.y = __expf(v.y - mrow);
        v.z = __expf(v.z - mrow);
        v.w = __expf(v.w - mrow);
        b4[j] = v;
        s += v.x + v.y + v.z + v.w;
    }
    #pragma unroll
    for (int o = 16; o > 0; o >>= 1) s += __shfl_xor_sync(0xffffffffu, s, o);
    if ((tid & 31) == 0) red[8 + (tid >> 5)] = s;
    __syncthreads();
    float srow = 0.0f;
    #pragma unroll
    for (int w = 0; w < 8; w++) srow += red[8 + w];
    const float inv = 1.0f / srow;

    #pragma unroll
    for (int j = tid; j < NV; j += 256) {
        float4 v = b4[j];
        v.x *= inv; v.y *= inv; v.z *= inv; v.w *= inv;
        r4[j] = v;
    }
}

// ---------------------------------------------------------------------------
// K3: O = P @ V, 2-pass fp16 (P = ph+pl scaled by 2^14, V = fp16 hi only).
// Pipelined: raw P staged in smem via cp.async (double use of single buffer),
// V double-buffered; per k-step B-frags shared across both passes.
// ---------------------------------------------------------------------------
#define AV_PRAW 0          // 32 KB fp32 staging (thread-major, xor by tid&7)
#define AV_AH   32768      // 16 KB fp16 P-hi
#define AV_AL   49152      // 16 KB fp16 P-lo
#define AV_V0   65536      // 16 KB fp16 V chunk buf 0
#define AV_V1   81920      // 16 KB fp16 V chunk buf 1
#define AV_BYTES 98304

__global__ __launch_bounds__(256, 2) void av_mma_kernel(const float* __restrict__ P,
                                                        float* __restrict__ O) {
    extern __shared__ char smem[];
    const uint32_t sb = smem_u32(smem);
    const int tid  = threadIdx.x;
    const int lane = tid & 31;
    const int wid  = tid >> 5;
    const int bm = blockIdx.x * 128;
    const int b  = blockIdx.y;
    const int wm = (wid >> 1) * 32;
    const int wn = (wid & 1) * 64;

    float c[2][8][4];
    #pragma unroll
    for (int i = 0; i < 2; i++)
        #pragma unroll
        for (int j = 0; j < 8; j++)
            #pragma unroll
            for (int q = 0; q < 4; q++) c[i][j][q] = 0.0f;

    const int lr  = tid >> 1;          // A row this thread owns (0..127)
    const int lc0 = (tid & 1) * 4;     // A fp16-chunk base (0 or 4)
    const int lsw = lr & 7;
    const int t7  = tid & 7;
    const float* prow = P + ((size_t)b * SEQ + bm + lr) * SEQ + (tid & 1) * 32;
    const size_t vbase = ((size_t)b * DIM + lr) * SEQ;

    const int s7 = lane & 7;
    const uint32_t a_row = (uint32_t)(wm + (lane & 15)) * 128;
    const int a_k = (lane >> 4) & 1;
    const uint32_t b_row = (uint32_t)(wn + (lane & 7) + ((lane >> 4) << 3)) * 128;
    const int b_k = (lane >> 3) & 1;

    // ---- prologue: stage chunk 0 ----
    #pragma unroll
    for (int i = 0; i < 8; i++)
        CP_ASYNC16(sb + AV_PRAW + tid * 128 + (uint32_t)((i ^ t7) << 4), prow + i * 4);
    #pragma unroll
    for (int j = 0; j < 4; j++) {
        const int ch = lc0 + j;
        CP_ASYNC16(sb + AV_V0 + lr * 128 + (uint32_t)((ch ^ lsw) << 4),
                   g_vh + vbase + ch * 8);
    }
    CP_ASYNC_WAIT_ALL();
    __syncthreads();

    for (int kc = 0; kc < 32; kc++) {
        const uint32_t vcur = sb + ((kc & 1) ? AV_V1 : AV_V0);
        const uint32_t vnxt = sb + ((kc & 1) ? AV_V0 : AV_V1);

        // ---- split own staged P (scaled) -> A hi/lo ----
        #pragma unroll
        for (int j = 0; j < 4; j++) {
            float4 x0 = *(const float4*)(smem + AV_PRAW + tid * 128 +
                                         (uint32_t)(((2 * j) ^ t7) << 4));
            float4 x1 = *(const float4*)(smem + AV_PRAW + tid * 128 +
                                         (uint32_t)(((2 * j + 1) ^ t7) << 4));
            uint4 hv, lv;
            split2h(x0.x * PSCALE, x0.y * PSCALE, hv.x, lv.x);
            split2h(x0.z * PSCALE, x0.w * PSCALE, hv.y, lv.y);
            split2h(x1.x * PSCALE, x1.y * PSCALE, hv.z, lv.z);
            split2h(x1.z * PSCALE, x1.w * PSCALE, hv.w, lv.w);
            const uint32_t doff = lr * 128 + (uint32_t)(((lc0 + j) ^ lsw) << 4);
            *(uint4*)(smem + AV_AH + doff) = hv;
            *(uint4*)(smem + AV_AL + doff) = lv;
        }
        __syncthreads();   // A visible; praw fully consumed; prev MMA done

        // ---- prefetch chunk kc+1 ----
        if (kc < 31) {
            const int kk = (kc + 1) * 64;
            #pragma unroll
            for (int i = 0; i < 8; i++)
                CP_ASYNC16(sb + AV_PRAW + tid * 128 + (uint32_t)((i ^ t7) << 4),
                           prow + kk + i * 4);
            #pragma unroll
            for (int j = 0; j < 4; j++) {
                const int ch = lc0 + j;
                CP_ASYNC16(vnxt + lr * 128 + (uint32_t)((ch ^ lsw) << 4),
                           g_vh + vbase + kk + ch * 8);
            }
            CP_COMMIT();
        }

        // ---- MMA: 2 passes sharing B-frags ----
        #pragma unroll
        for (int ks = 0; ks < 4; ks++) {
            uint32_t bf[4][4], ah[2][4], al[2][4];
            const uint32_t bc = (uint32_t)(((2 * ks + b_k) ^ s7) << 4);
            #pragma unroll
            for (int nt = 0; nt < 4; nt++)
                ldmx4(bf[nt], vcur + b_row + nt * 2048 + bc);
            const uint32_t ac = (uint32_t)(((2 * ks + a_k) ^ s7) << 4);
            ldmx4(ah[0], sb + AV_AH + a_row + ac);
            ldmx4(ah[1], sb + AV_AH + a_row + 2048 + ac);
            ldmx4(al[0], sb + AV_AL + a_row + ac);
            ldmx4(al[1], sb + AV_AL + a_row + 2048 + ac);
            #pragma unroll
            for (int mt = 0; mt < 2; mt++)
                #pragma unroll
                for (int nb = 0; nb < 8; nb++)
                    mma16816_fp(c[mt][nb], ah[mt], &bf[nb >> 1][(nb & 1) * 2]);
            #pragma unroll
            for (int mt = 0; mt < 2; mt++)
                #pragma unroll
                for (int nb = 0; nb < 8; nb++)
                    mma16816_fp(c[mt][nb], al[mt], &bf[nb >> 1][(nb & 1) * 2]);
        }

        if (kc < 31) CP_WAIT0();
        __syncthreads();   // MMA done (A, vcur free); prefetched data visible
    }

    const int g = lane >> 2, t = lane & 3;
    #pragma unroll
    for (int mt = 0; mt < 2; mt++) {
        const size_t r0 = (size_t)b * SEQ + bm + wm + mt * 16 + g;
        #pragma unroll
        for (int nb = 0; nb < 8; nb++) {
            const int col = wn + nb * 8 + 2 * t;
            *(float2*)&O[r0 * DIM + col] =
                make_float2(c[mt][nb][0] * PSCALE_I, c[mt][nb][1] * PSCALE_I);
            *(float2*)&O[(r0 + 8) * DIM + col] =
                make_float2(c[mt][nb][2] * PSCALE_I, c[mt][nb][3] * PSCALE_I);
        }
    }
}

// ---------------------------------------------------------------------------
// Launch: out = [ output (B*N*D) | attn (B*N*N) ]
// ---------------------------------------------------------------------------
extern "C" void kernel_launch(void* const* d_in, const int* in_sizes, int n_in,
                              void* d_out, int out_size) {
    const float* q = (const float*)d_in[0];
    const float* k = (const float*)d_in[1];
    const float* v = (const float*)d_in[2];
    float* out  = (float*)d_out;
    float* attn = out + (size_t)BATCH * SEQ * DIM;

    cudaFuncSetAttribute(scores_mma_kernel,
                         cudaFuncAttributeMaxDynamicSharedMemorySize, SC_BYTES);
    cudaFuncSetAttribute(av_mma_kernel,
                         cudaFuncAttributeMaxDynamicSharedMemorySize, AV_BYTES);

    const int n4 = BATCH * SEQ * DIM / 4;
    split_kernel<0><<<(n4 + 255) / 256, 256>>>(q, n4);
    split_kernel<1><<<(n4 + 255) / 256, 256>>>(k, n4);

    dim3 gv(SEQ / 32, DIM / 32, BATCH);
    vtrans_kernel<<<gv, 256>>>(v);

    dim3 g1(SEQ / 128, SEQ / 128, BATCH);
    scores_mma_kernel<<<g1, 256, SC_BYTES>>>(attn);

    softmax_kernel<<<BATCH * SEQ, 256>>>(attn);

    dim3 g3(SEQ / 128, BATCH);
    av_mma_kernel<<<g3, 256, AV_BYTES>>>(attn, out);
}

// round 12
// speedup vs baseline: 2.4773x; 1.0049x over previous
#include <cuda_runtime.h>
#include <cuda_bf16.h>
#include <cuda_fp16.h>
#include <cstdint>

#define BATCH 16
#define SEQ   2048
#define DIM   128
#define PSCALE   16384.0f
#define PSCALE_I 6.103515625e-05f   // 1/16384

// ---------------------------------------------------------------------------
// Static device scratch: split bf16 Q/K, fp16 transposed V, row-sum partials.
// ---------------------------------------------------------------------------
static __device__ __align__(1024) __nv_bfloat16 g_qh[BATCH * SEQ * DIM];
static __device__ __align__(1024) __nv_bfloat16 g_ql[BATCH * SEQ * DIM];
static __device__ __align__(1024) __nv_bfloat16 g_kh[BATCH * SEQ * DIM];
static __device__ __align__(1024) __nv_bfloat16 g_kl[BATCH * SEQ * DIM];
static __device__ __align__(1024) __half        g_vh[BATCH * DIM * SEQ]; // [b][d][n]
static __device__ __align__(1024) float         g_rowpart[BATCH * SEQ * 8];
static __device__ __align__(1024) float         g_inv[BATCH * SEQ];

// ---------------------------------------------------------------------------
// Helpers (baseline PTX only: ldmatrix / mma.sync / cp.async)
// ---------------------------------------------------------------------------
__device__ __forceinline__ uint32_t smem_u32(const void* p) {
    uint32_t a;
    asm("{ .reg .u64 t; cvta.to.shared.u64 t, %1; cvt.u32.u64 %0, t; }"
        : "=r"(a) : "l"(p));
    return a;
}

#define CP_ASYNC16(dst_u32, src_ptr) \
    asm volatile("cp.async.cg.shared.global [%0], [%1], 16;" \
                 :: "r"(dst_u32), "l"(src_ptr))
#define CP_COMMIT()  asm volatile("cp.async.commit_group;" ::: "memory")
#define CP_WAIT0()   asm volatile("cp.async.wait_group 0;" ::: "memory")
#define CP_WAIT1()   asm volatile("cp.async.wait_group 1;" ::: "memory")
#define CP_ASYNC_WAIT_ALL() \
    asm volatile("cp.async.commit_group;\ncp.async.wait_group 0;" ::: "memory")

__device__ __forceinline__ void ldmx4(uint32_t* r, uint32_t addr) {
    asm volatile("ldmatrix.sync.aligned.m8n8.x4.shared.b16 {%0,%1,%2,%3}, [%4];"
                 : "=r"(r[0]), "=r"(r[1]), "=r"(r[2]), "=r"(r[3]) : "r"(addr));
}

__device__ __forceinline__ void mma16816_bf(float* c, const uint32_t* a,
                                            const uint32_t* b) {
    asm volatile(
        "mma.sync.aligned.m16n8k16.row.col.f32.bf16.bf16.f32 "
        "{%0,%1,%2,%3}, {%4,%5,%6,%7}, {%8,%9}, {%0,%1,%2,%3};"
        : "+f"(c[0]), "+f"(c[1]), "+f"(c[2]), "+f"(c[3])
        : "r"(a[0]), "r"(a[1]), "r"(a[2]), "r"(a[3]), "r"(b[0]), "r"(b[1]));
}

__device__ __forceinline__ void mma16816_fp(float* c, const uint32_t* a,
                                            const uint32_t* b) {
    asm volatile(
        "mma.sync.aligned.m16n8k16.row.col.f32.f16.f16.f32 "
        "{%0,%1,%2,%3}, {%4,%5,%6,%7}, {%8,%9}, {%0,%1,%2,%3};"
        : "+f"(c[0]), "+f"(c[1]), "+f"(c[2]), "+f"(c[3])
        : "r"(a[0]), "r"(a[1]), "r"(a[2]), "r"(a[3]), "r"(b[0]), "r"(b[1]));
}

__device__ __forceinline__ void split2(float a, float b, uint32_t& h, uint32_t& l) {
    __nv_bfloat16 ha = __float2bfloat16_rn(a);
    __nv_bfloat16 hb = __float2bfloat16_rn(b);
    __nv_bfloat16 la = __float2bfloat16_rn(a - __bfloat162float(ha));
    __nv_bfloat16 lb = __float2bfloat16_rn(b - __bfloat162float(hb));
    h = (uint32_t)__bfloat16_as_ushort(ha) | ((uint32_t)__bfloat16_as_ushort(hb) << 16);
    l = (uint32_t)__bfloat16_as_ushort(la) | ((uint32_t)__bfloat16_as_ushort(lb) << 16);
}

__device__ __forceinline__ void split2h(float a, float b, uint32_t& h, uint32_t& l) {
    __half ha = __float2half_rn(a);
    __half hb = __float2half_rn(b);
    __half la = __float2half_rn(a - __half2float(ha));
    __half lb = __float2half_rn(b - __half2float(hb));
    h = (uint32_t)__half_as_ushort(ha) | ((uint32_t)__half_as_ushort(hb) << 16);
    l = (uint32_t)__half_as_ushort(la) | ((uint32_t)__half_as_ushort(lb) << 16);
}

// ---------------------------------------------------------------------------
// K0a: elementwise split fp32 -> (hi, lo) bf16 (ISK: 0 = Q, 1 = K)
// ---------------------------------------------------------------------------
template <int ISK>
__global__ __launch_bounds__(256) void split_kernel(const float* __restrict__ src,
                                                    int n4) {
    int i = blockIdx.x * 256 + threadIdx.x;
    if (i >= n4) return;
    __nv_bfloat16* dh = ISK ? g_kh : g_qh;
    __nv_bfloat16* dl = ISK ? g_kl : g_ql;
    float4 x = ((const float4*)src)[i];
    uint32_t h0, l0, h1, l1;
    split2(x.x, x.y, h0, l0);
    split2(x.z, x.w, h1, l1);
    ((uint2*)dh)[i] = make_uint2(h0, h1);
    ((uint2*)dl)[i] = make_uint2(l0, l1);
}

// ---------------------------------------------------------------------------
// K0b: V transpose to fp16
// ---------------------------------------------------------------------------
__global__ __launch_bounds__(256) void vtrans_kernel(const float* __restrict__ V) {
    __shared__ float tile[32][33];
    const int b  = blockIdx.z;
    const int n0 = blockIdx.x * 32;
    const int d0 = blockIdx.y * 32;
    const int tx = threadIdx.x & 31;
    const int ty = threadIdx.x >> 5;
    #pragma unroll
    for (int r = 0; r < 4; r++)
        tile[ty + 8 * r][tx] = V[((size_t)b * SEQ + n0 + ty + 8 * r) * DIM + d0 + tx];
    __syncthreads();
    #pragma unroll
    for (int r = 0; r < 4; r++) {
        int d = d0 + ty + 8 * r;
        float x = tile[tx][ty + 8 * r];
        g_vh[((size_t)b * DIM + d) * SEQ + n0 + tx] = __float2half_rn(x);
    }
}

// ---------------------------------------------------------------------------
// K1: fused scores + exp + partial row sums.
// CTA 128(m) x 256(n), 512 threads (16 warps, warp tile 32x64).
// Writes e = exp(q.k) to P and per-(row, n-tile) sums to g_rowpart.
// Both 64-wide K-chunks double-buffered; all cp.async issued up front.
// ---------------------------------------------------------------------------
#define ST_STRIDE 98304   // per-stage: QH 16K | QL 16K | KH 32K | KL 32K
#define SC_BYTES  196608

__global__ __launch_bounds__(512, 1) void scores_mma_kernel(float* __restrict__ P) {
    extern __shared__ char smem[];
    const uint32_t sb = smem_u32(smem);
    const int tid  = threadIdx.x;
    const int lane = tid & 31;
    const int wid  = tid >> 5;
    const int b  = blockIdx.z;
    const int bm = blockIdx.y * 128;
    const int bn = blockIdx.x * 256;
    const int wm = (wid >> 2) * 32;
    const int wn = (wid & 3) * 64;

    float c[2][8][4];
    #pragma unroll
    for (int i = 0; i < 2; i++)
        #pragma unroll
        for (int j = 0; j < 8; j++)
            #pragma unroll
            for (int q = 0; q < 4; q++) c[i][j][q] = 0.0f;

    // ---- issue loads for BOTH stages up front ----
    {
        const int qr = tid >> 2;                 // 0..127
        const int qq = tid & 3;                  // quarter: 2 units each
        const size_t qoff = ((size_t)b * SEQ + bm + qr) * DIM + qq * 16;
        const int kr = tid >> 1;                 // 0..255
        const int kh = tid & 1;                  // half: 4 units each
        const size_t koff = ((size_t)b * SEQ + bn + kr) * DIM + kh * 32;
        #pragma unroll
        for (int s = 0; s < 2; s++) {
            const uint32_t st = sb + s * ST_STRIDE;
            const int kk = s * 64;
            #pragma unroll
            for (int j = 0; j < 2; j++) {
                const int u = qq * 2 + j;
                const uint32_t qd = st + qr * 128 + (uint32_t)((u ^ (qr & 7)) << 4);
                CP_ASYNC16(qd,         g_qh + qoff + kk + j * 8);
                CP_ASYNC16(qd + 16384, g_ql + qoff + kk + j * 8);
            }
            #pragma unroll
            for (int j = 0; j < 4; j++) {
                const int u = kh * 4 + j;
                const uint32_t kd = st + 32768 + kr * 128 +
                                    (uint32_t)((u ^ (kr & 7)) << 4);
                CP_ASYNC16(kd,         g_kh + koff + kk + j * 8);
                CP_ASYNC16(kd + 32768, g_kl + koff + kk + j * 8);
            }
            CP_COMMIT();
        }
    }

    const int s7 = lane & 7;
    const uint32_t a_row = (uint32_t)(wm + (lane & 15)) * 128;
    const int a_k = (lane >> 4) & 1;
    const uint32_t b_row = (uint32_t)(wn + (lane & 7) + ((lane >> 4) << 3)) * 128;
    const int b_k = (lane >> 3) & 1;

    #pragma unroll
    for (int s = 0; s < 2; s++) {
        if (s == 0) CP_WAIT1(); else CP_WAIT0();
        __syncthreads();
        const uint32_t st = sb + s * ST_STRIDE;
        #pragma unroll
        for (int pass = 0; pass < 3; pass++) {
            const uint32_t Ab = st + (pass == 2 ? 16384 : 0);
            const uint32_t Bb = st + 32768 + (pass == 1 ? 32768 : 0);
            #pragma unroll
            for (int ks = 0; ks < 4; ks++) {
                uint32_t a[2][4], bf[4][4];
                const uint32_t ac = (uint32_t)(((2 * ks + a_k) ^ s7) << 4);
                ldmx4(a[0], Ab + a_row + ac);
                ldmx4(a[1], Ab + a_row + 2048 + ac);
                const uint32_t bc = (uint32_t)(((2 * ks + b_k) ^ s7) << 4);
                #pragma unroll
                for (int nt = 0; nt < 4; nt++)
                    ldmx4(bf[nt], Bb + b_row + nt * 2048 + bc);
                #pragma unroll
                for (int mt = 0; mt < 2; mt++)
                    #pragma unroll
                    for (int nb = 0; nb < 8; nb++)
                        mma16816_bf(c[mt][nb], a[mt], &bf[nb >> 1][(nb & 1) * 2]);
            }
        }
    }

    // ---- epilogue: exp in-place, per-row partial sums, store e ----
    float rs[2][2];
    #pragma unroll
    for (int mt = 0; mt < 2; mt++) {
        float s01 = 0.0f, s23 = 0.0f;
        #pragma unroll
        for (int nb = 0; nb < 8; nb++) {
            c[mt][nb][0] = __expf(c[mt][nb][0]);
            c[mt][nb][1] = __expf(c[mt][nb][1]);
            c[mt][nb][2] = __expf(c[mt][nb][2]);
            c[mt][nb][3] = __expf(c[mt][nb][3]);
            s01 += c[mt][nb][0] + c[mt][nb][1];
            s23 += c[mt][nb][2] + c[mt][nb][3];
        }
        rs[mt][0] = s01;
        rs[mt][1] = s23;
    }
    #pragma unroll
    for (int mt = 0; mt < 2; mt++)
        #pragma unroll
        for (int h = 0; h < 2; h++) {
            float v = rs[mt][h];
            v += __shfl_xor_sync(0xffffffffu, v, 1);
            v += __shfl_xor_sync(0xffffffffu, v, 2);
            rs[mt][h] = v;
        }

    __syncthreads();                 // stage buffers dead -> reuse as ps[4][128]
    float* ps = (float*)smem;
    const int g = lane >> 2, t = lane & 3;
    if (t == 0) {
        const int slot = (wid & 3) * 128;
        #pragma unroll
        for (int mt = 0; mt < 2; mt++) {
            ps[slot + wm + mt * 16 + g]     = rs[mt][0];
            ps[slot + wm + mt * 16 + g + 8] = rs[mt][1];
        }
    }
    __syncthreads();
    if (tid < 128) {
        float tot = ps[tid] + ps[128 + tid] + ps[256 + tid] + ps[384 + tid];
        g_rowpart[((size_t)(b * SEQ + bm + tid)) * 8 + blockIdx.x] = tot;
    }

    #pragma unroll
    for (int mt = 0; mt < 2; mt++) {
        const size_t r0 = (size_t)b * SEQ + bm + wm + mt * 16 + g;
        #pragma unroll
        for (int nb = 0; nb < 8; nb++) {
            const int col = bn + wn + nb * 8 + 2 * t;
            *(float2*)&P[r0 * SEQ + col]       = make_float2(c[mt][nb][0], c[mt][nb][1]);
            *(float2*)&P[(r0 + 8) * SEQ + col] = make_float2(c[mt][nb][2], c[mt][nb][3]);
        }
    }
}

// ---------------------------------------------------------------------------
// K2: row-sum inverse (deterministic 8-partial reduce)
// ---------------------------------------------------------------------------
__global__ __launch_bounds__(256) void inv_kernel() {
    const int r = blockIdx.x * 256 + threadIdx.x;
    if (r >= BATCH * SEQ) return;
    const float4* p = (const float4*)(g_rowpart + (size_t)r * 8);
    float4 a = p[0], bq = p[1];
    g_inv[r] = 1.0f / (a.x + a.y + a.z + a.w + bq.x + bq.y + bq.z + bq.w);
}

// ---------------------------------------------------------------------------
// K3: O = P @ V (2-pass fp16) + in-flight normalization + P writeback.
// Reads e-matrix, p = e * inv_row; writes p to P (attn output) and feeds
// p * 2^14 hi/lo fp16 into the MMA.
// ---------------------------------------------------------------------------
#define AV_PRAW 0
#define AV_AH   32768
#define AV_AL   49152
#define AV_V0   65536
#define AV_V1   81920
#define AV_BYTES 98304

__global__ __launch_bounds__(256, 2) void av_mma_kernel(float* __restrict__ P,
                                                        float* __restrict__ O) {
    extern __shared__ char smem[];
    const uint32_t sb = smem_u32(smem);
    const int tid  = threadIdx.x;
    const int lane = tid & 31;
    const int wid  = tid >> 5;
    const int bm = blockIdx.x * 128;
    const int b  = blockIdx.y;
    const int wm = (wid >> 1) * 32;
    const int wn = (wid & 1) * 64;

    float c[2][8][4];
    #pragma unroll
    for (int i = 0; i < 2; i++)
        #pragma unroll
        for (int j = 0; j < 8; j++)
            #pragma unroll
            for (int q = 0; q < 4; q++) c[i][j][q] = 0.0f;

    const int lr  = tid >> 1;
    const int lc0 = (tid & 1) * 4;
    const int lsw = lr & 7;
    const int t7  = tid & 7;
    float* prow = P + ((size_t)b * SEQ + bm + lr) * SEQ + (tid & 1) * 32;
    const size_t vbase = ((size_t)b * DIM + lr) * SEQ;
    const float inv_r = g_inv[b * SEQ + bm + lr];
    const float fs    = inv_r * PSCALE;

    const int s7 = lane & 7;
    const uint32_t a_row = (uint32_t)(wm + (lane & 15)) * 128;
    const int a_k = (lane >> 4) & 1;
    const uint32_t b_row = (uint32_t)(wn + (lane & 7) + ((lane >> 4) << 3)) * 128;
    const int b_k = (lane >> 3) & 1;

    // ---- prologue: stage chunk 0 ----
    #pragma unroll
    for (int i = 0; i < 8; i++)
        CP_ASYNC16(sb + AV_PRAW + tid * 128 + (uint32_t)((i ^ t7) << 4), prow + i * 4);
    #pragma unroll
    for (int j = 0; j < 4; j++) {
        const int ch = lc0 + j;
        CP_ASYNC16(sb + AV_V0 + lr * 128 + (uint32_t)((ch ^ lsw) << 4),
                   g_vh + vbase + ch * 8);
    }
    CP_ASYNC_WAIT_ALL();
    __syncthreads();

    for (int kc = 0; kc < 32; kc++) {
        const int kk = kc * 64;
        const uint32_t vcur = sb + ((kc & 1) ? AV_V1 : AV_V0);
        const uint32_t vnxt = sb + ((kc & 1) ? AV_V0 : AV_V1);

        // ---- normalize staged e -> p; write P; split p*2^14 -> A hi/lo ----
        #pragma unroll
        for (int j = 0; j < 4; j++) {
            float4 x0 = *(const float4*)(smem + AV_PRAW + tid * 128 +
                                         (uint32_t)(((2 * j) ^ t7) << 4));
            float4 x1 = *(const float4*)(smem + AV_PRAW + tid * 128 +
                                         (uint32_t)(((2 * j + 1) ^ t7) << 4));
            *(float4*)(prow + kk + 8 * j) =
                make_float4(x0.x * inv_r, x0.y * inv_r, x0.z * inv_r, x0.w * inv_r);
            *(float4*)(prow + kk + 8 * j + 4) =
                make_float4(x1.x * inv_r, x1.y * inv_r, x1.z * inv_r, x1.w * inv_r);
            uint4 hv, lv;
            split2h(x0.x * fs, x0.y * fs, hv.x, lv.x);
            split2h(x0.z * fs, x0.w * fs, hv.y, lv.y);
            split2h(x1.x * fs, x1.y * fs, hv.z, lv.z);
            split2h(x1.z * fs, x1.w * fs, hv.w, lv.w);
            const uint32_t doff = lr * 128 + (uint32_t)(((lc0 + j) ^ lsw) << 4);
            *(uint4*)(smem + AV_AH + doff) = hv;
            *(uint4*)(smem + AV_AL + doff) = lv;
        }
        __syncthreads();

        // ---- prefetch chunk kc+1 ----
        if (kc < 31) {
            const int kn = kk + 64;
            #pragma unroll
            for (int i = 0; i < 8; i++)
                CP_ASYNC16(sb + AV_PRAW + tid * 128 + (uint32_t)((i ^ t7) << 4),
                           prow + kn + i * 4);
            #pragma unroll
            for (int j = 0; j < 4; j++) {
                const int ch = lc0 + j;
                CP_ASYNC16(vnxt + lr * 128 + (uint32_t)((ch ^ lsw) << 4),
                           g_vh + vbase + kn + ch * 8);
            }
            CP_COMMIT();
        }

        // ---- MMA: 2 passes sharing B-frags ----
        #pragma unroll
        for (int ks = 0; ks < 4; ks++) {
            uint32_t bf[4][4], ah[2][4], al[2][4];
            const uint32_t bc = (uint32_t)(((2 * ks + b_k) ^ s7) << 4);
            #pragma unroll
            for (int nt = 0; nt < 4; nt++)
                ldmx4(bf[nt], vcur + b_row + nt * 2048 + bc);
            const uint32_t ac = (uint32_t)(((2 * ks + a_k) ^ s7) << 4);
            ldmx4(ah[0], sb + AV_AH + a_row + ac);
            ldmx4(ah[1], sb + AV_AH + a_row + 2048 + ac);
            ldmx4(al[0], sb + AV_AL + a_row + ac);
            ldmx4(al[1], sb + AV_AL + a_row + 2048 + ac);
            #pragma unroll
            for (int mt = 0; mt < 2; mt++)
                #pragma unroll
                for (int nb = 0; nb < 8; nb++)
                    mma16816_fp(c[mt][nb], ah[mt], &bf[nb >> 1][(nb & 1) * 2]);
            #pragma unroll
            for (int mt = 0; mt < 2; mt++)
                #pragma unroll
                for (int nb = 0; nb < 8; nb++)
                    mma16816_fp(c[mt][nb], al[mt], &bf[nb >> 1][(nb & 1) * 2]);
        }

        if (kc < 31) CP_WAIT0();
        __syncthreads();
    }

    const int g = lane >> 2, t = lane & 3;
    #pragma unroll
    for (int mt = 0; mt < 2; mt++) {
        const size_t r0 = (size_t)b * SEQ + bm + wm + mt * 16 + g;
        #pragma unroll
        for (int nb = 0; nb < 8; nb++) {
            const int col = wn + nb * 8 + 2 * t;
            *(float2*)&O[r0 * DIM + col] =
                make_float2(c[mt][nb][0] * PSCALE_I, c[mt][nb][1] * PSCALE_I);
            *(float2*)&O[(r0 + 8) * DIM + col] =
                make_float2(c[mt][nb][2] * PSCALE_I, c[mt][nb][3] * PSCALE_I);
        }
    }
}

// ---------------------------------------------------------------------------
// Launch: out = [ output (B*N*D) | attn (B*N*N) ]
// ---------------------------------------------------------------------------
extern "C" void kernel_launch(void* const* d_in, const int* in_sizes, int n_in,
                              void* d_out, int out_size) {
    const float* q = (const float*)d_in[0];
    const float* k = (const float*)d_in[1];
    const float* v = (const float*)d_in[2];
    float* out  = (float*)d_out;
    float* attn = out + (size_t)BATCH * SEQ * DIM;

    cudaFuncSetAttribute(scores_mma_kernel,
                         cudaFuncAttributeMaxDynamicSharedMemorySize, SC_BYTES);
    cudaFuncSetAttribute(av_mma_kernel,
                         cudaFuncAttributeMaxDynamicSharedMemorySize, AV_BYTES);

    const int n4 = BATCH * SEQ * DIM / 4;
    split_kernel<0><<<(n4 + 255) / 256, 256>>>(q, n4);
    split_kernel<1><<<(n4 + 255) / 256, 256>>>(k, n4);

    dim3 gv(SEQ / 32, DIM / 32, BATCH);
    vtrans_kernel<<<gv, 256>>>(v);

    dim3 g1(SEQ / 256, SEQ / 128, BATCH);   // 8 x 16 x 16 = 2048 CTAs
    scores_mma_kernel<<<g1, 512, SC_BYTES>>>(attn);

    inv_kernel<<<(BATCH * SEQ) / 256, 256>>>();

    dim3 g3(SEQ / 128, BATCH);
    av_mma_kernel<<<g3, 256, AV_BYTES>>>(attn, out);
}

// round 15
// speedup vs baseline: 2.6808x; 1.0821x over previous
#include <cuda_runtime.h>
#include <cuda_bf16.h>
#include <cuda_fp16.h>
#include <cstdint>

#define BATCH 16
#define SEQ   2048
#define DIM   128
#define PSCALE   16384.0f
#define PSCALE_I 6.103515625e-05f   // 1/16384

// ---------------------------------------------------------------------------
// Static device scratch: split bf16 Q/K, fp16 transposed V, row-sum partials.
// ---------------------------------------------------------------------------
static __device__ __align__(1024) __nv_bfloat16 g_qh[BATCH * SEQ * DIM];
static __device__ __align__(1024) __nv_bfloat16 g_ql[BATCH * SEQ * DIM];
static __device__ __align__(1024) __nv_bfloat16 g_kh[BATCH * SEQ * DIM];
static __device__ __align__(1024) __nv_bfloat16 g_kl[BATCH * SEQ * DIM];
static __device__ __align__(1024) __half        g_vh[BATCH * DIM * SEQ]; // [b][d][n]
static __device__ __align__(1024) float         g_rowpart[BATCH * SEQ * 8];
static __device__ __align__(1024) float         g_inv[BATCH * SEQ];

// ---------------------------------------------------------------------------
// Helpers (baseline PTX only: ldmatrix / mma.sync / cp.async)
// ---------------------------------------------------------------------------
__device__ __forceinline__ uint32_t smem_u32(const void* p) {
    uint32_t a;
    asm("{ .reg .u64 t; cvta.to.shared.u64 t, %1; cvt.u32.u64 %0, t; }"
        : "=r"(a) : "l"(p));
    return a;
}

#define CP_ASYNC16(dst_u32, src_ptr) \
    asm volatile("cp.async.cg.shared.global [%0], [%1], 16;" \
                 :: "r"(dst_u32), "l"(src_ptr))
#define CP_COMMIT()  asm volatile("cp.async.commit_group;" ::: "memory")
#define CP_WAIT0()   asm volatile("cp.async.wait_group 0;" ::: "memory")
#define CP_WAIT1()   asm volatile("cp.async.wait_group 1;" ::: "memory")
#define CP_WAIT2()   asm volatile("cp.async.wait_group 2;" ::: "memory")

__device__ __forceinline__ void ldmx4(uint32_t* r, uint32_t addr) {
    asm volatile("ldmatrix.sync.aligned.m8n8.x4.shared.b16 {%0,%1,%2,%3}, [%4];"
                 : "=r"(r[0]), "=r"(r[1]), "=r"(r[2]), "=r"(r[3]) : "r"(addr));
}

__device__ __forceinline__ void mma16816_bf(float* c, const uint32_t* a,
                                            const uint32_t* b) {
    asm volatile(
        "mma.sync.aligned.m16n8k16.row.col.f32.bf16.bf16.f32 "
        "{%0,%1,%2,%3}, {%4,%5,%6,%7}, {%8,%9}, {%0,%1,%2,%3};"
        : "+f"(c[0]), "+f"(c[1]), "+f"(c[2]), "+f"(c[3])
        : "r"(a[0]), "r"(a[1]), "r"(a[2]), "r"(a[3]), "r"(b[0]), "r"(b[1]));
}

__device__ __forceinline__ void mma16816_fp(float* c, const uint32_t* a,
                                            const uint32_t* b) {
    asm volatile(
        "mma.sync.aligned.m16n8k16.row.col.f32.f16.f16.f32 "
        "{%0,%1,%2,%3}, {%4,%5,%6,%7}, {%8,%9}, {%0,%1,%2,%3};"
        : "+f"(c[0]), "+f"(c[1]), "+f"(c[2]), "+f"(c[3])
        : "r"(a[0]), "r"(a[1]), "r"(a[2]), "r"(a[3]), "r"(b[0]), "r"(b[1]));
}

__device__ __forceinline__ void split2(float a, float b, uint32_t& h, uint32_t& l) {
    __nv_bfloat16 ha = __float2bfloat16_rn(a);
    __nv_bfloat16 hb = __float2bfloat16_rn(b);
    __nv_bfloat16 la = __float2bfloat16_rn(a - __bfloat162float(ha));
    __nv_bfloat16 lb = __float2bfloat16_rn(b - __bfloat162float(hb));
    h = (uint32_t)__bfloat16_as_ushort(ha) | ((uint32_t)__bfloat16_as_ushort(hb) << 16);
    l = (uint32_t)__bfloat16_as_ushort(la) | ((uint32_t)__bfloat16_as_ushort(lb) << 16);
}

__device__ __forceinline__ void split2h(float a, float b, uint32_t& h, uint32_t& l) {
    __half ha = __float2half_rn(a);
    __half hb = __float2half_rn(b);
    __half la = __float2half_rn(a - __half2float(ha));
    __half lb = __float2half_rn(b - __half2float(hb));
    h = (uint32_t)__half_as_ushort(ha) | ((uint32_t)__half_as_ushort(hb) << 16);
    l = (uint32_t)__half_as_ushort(la) | ((uint32_t)__half_as_ushort(lb) << 16);
}

// ---------------------------------------------------------------------------
// K0a: elementwise split fp32 -> (hi, lo) bf16 (ISK: 0 = Q, 1 = K)
// ---------------------------------------------------------------------------
template <int ISK>
__global__ __launch_bounds__(256) void split_kernel(const float* __restrict__ src,
                                                    int n4) {
    int i = blockIdx.x * 256 + threadIdx.x;
    if (i >= n4) return;
    __nv_bfloat16* dh = ISK ? g_kh : g_qh;
    __nv_bfloat16* dl = ISK ? g_kl : g_ql;
    float4 x = ((const float4*)src)[i];
    uint32_t h0, l0, h1, l1;
    split2(x.x, x.y, h0, l0);
    split2(x.z, x.w, h1, l1);
    ((uint2*)dh)[i] = make_uint2(h0, h1);
    ((uint2*)dl)[i] = make_uint2(l0, l1);
}

// ---------------------------------------------------------------------------
// K0b: V transpose to fp16
// ---------------------------------------------------------------------------
__global__ __launch_bounds__(256) void vtrans_kernel(const float* __restrict__ V) {
    __shared__ float tile[32][33];
    const int b  = blockIdx.z;
    const int n0 = blockIdx.x * 32;
    const int d0 = blockIdx.y * 32;
    const int tx = threadIdx.x & 31;
    const int ty = threadIdx.x >> 5;
    #pragma unroll
    for (int r = 0; r < 4; r++)
        tile[ty + 8 * r][tx] = V[((size_t)b * SEQ + n0 + ty + 8 * r) * DIM + d0 + tx];
    __syncthreads();
    #pragma unroll
    for (int r = 0; r < 4; r++) {
        int d = d0 + ty + 8 * r;
        float x = tile[tx][ty + 8 * r];
        g_vh[((size_t)b * DIM + d) * SEQ + n0 + tx] = __float2half_rn(x);
    }
}

// ---------------------------------------------------------------------------
// K1: fused scores + exp + partial row sums.
// CTA 128(m) x 256(n), 512 threads (16 warps, warp tile 32x64).
// Per k-step pass order hh -> lh -> hl with fragment reuse:
//   Qh frags serve hh+hl, Kh frags serve hh+lh  => 12 ldmx4/ks (was 18).
// ---------------------------------------------------------------------------
#define ST_STRIDE 98304   // per-stage: QH 16K | QL 16K | KH 32K | KL 32K
#define SC_BYTES  196608

__global__ __launch_bounds__(512, 1) void scores_mma_kernel(float* __restrict__ P) {
    extern __shared__ char smem[];
    const uint32_t sb = smem_u32(smem);
    const int tid  = threadIdx.x;
    const int lane = tid & 31;
    const int wid  = tid >> 5;
    const int b  = blockIdx.z;
    const int bm = blockIdx.y * 128;
    const int bn = blockIdx.x * 256;
    const int wm = (wid >> 2) * 32;
    const int wn = (wid & 3) * 64;

    float c[2][8][4];
    #pragma unroll
    for (int i = 0; i < 2; i++)
        #pragma unroll
        for (int j = 0; j < 8; j++)
            #pragma unroll
            for (int q = 0; q < 4; q++) c[i][j][q] = 0.0f;

    // ---- issue loads for BOTH stages up front ----
    {
        const int qr = tid >> 2;
        const int qq = tid & 3;
        const size_t qoff = ((size_t)b * SEQ + bm + qr) * DIM + qq * 16;
        const int kr = tid >> 1;
        const int kh = tid & 1;
        const size_t koff = ((size_t)b * SEQ + bn + kr) * DIM + kh * 32;
        #pragma unroll
        for (int s = 0; s < 2; s++) {
            const uint32_t st = sb + s * ST_STRIDE;
            const int kk = s * 64;
            #pragma unroll
            for (int j = 0; j < 2; j++) {
                const int u = qq * 2 + j;
                const uint32_t qd = st + qr * 128 + (uint32_t)((u ^ (qr & 7)) << 4);
                CP_ASYNC16(qd,         g_qh + qoff + kk + j * 8);
                CP_ASYNC16(qd + 16384, g_ql + qoff + kk + j * 8);
            }
            #pragma unroll
            for (int j = 0; j < 4; j++) {
                const int u = kh * 4 + j;
                const uint32_t kd = st + 32768 + kr * 128 +
                                    (uint32_t)((u ^ (kr & 7)) << 4);
                CP_ASYNC16(kd,         g_kh + koff + kk + j * 8);
                CP_ASYNC16(kd + 32768, g_kl + koff + kk + j * 8);
            }
            CP_COMMIT();
        }
    }

    const int s7 = lane & 7;
    const uint32_t a_row = (uint32_t)(wm + (lane & 15)) * 128;
    const int a_k = (lane >> 4) & 1;
    const uint32_t b_row = (uint32_t)(wn + (lane & 7) + ((lane >> 4) << 3)) * 128;
    const int b_k = (lane >> 3) & 1;

    #pragma unroll
    for (int s = 0; s < 2; s++) {
        if (s == 0) CP_WAIT1(); else CP_WAIT0();
        __syncthreads();
        const uint32_t Qh = sb + s * ST_STRIDE;
        const uint32_t Ql = Qh + 16384;
        const uint32_t Kh = Qh + 32768;
        const uint32_t Kl = Qh + 65536;
        #pragma unroll
        for (int ks = 0; ks < 4; ks++) {
            uint32_t aqh[2][4], aql[2][4], bk[4][4];
            const uint32_t ac = (uint32_t)(((2 * ks + a_k) ^ s7) << 4);
            const uint32_t bc = (uint32_t)(((2 * ks + b_k) ^ s7) << 4);
            // hh
            ldmx4(aqh[0], Qh + a_row + ac);
            ldmx4(aqh[1], Qh + a_row + 2048 + ac);
            #pragma unroll
            for (int nt = 0; nt < 4; nt++)
                ldmx4(bk[nt], Kh + b_row + nt * 2048 + bc);
            #pragma unroll
            for (int mt = 0; mt < 2; mt++)
                #pragma unroll
                for (int nb = 0; nb < 8; nb++)
                    mma16816_bf(c[mt][nb], aqh[mt], &bk[nb >> 1][(nb & 1) * 2]);
            // lh (reuse Kh frags)
            ldmx4(aql[0], Ql + a_row + ac);
            ldmx4(aql[1], Ql + a_row + 2048 + ac);
            #pragma unroll
            for (int mt = 0; mt < 2; mt++)
                #pragma unroll
                for (int nb = 0; nb < 8; nb++)
                    mma16816_bf(c[mt][nb], aql[mt], &bk[nb >> 1][(nb & 1) * 2]);
            // hl (reuse Qh frags)
            #pragma unroll
            for (int nt = 0; nt < 4; nt++)
                ldmx4(bk[nt], Kl + b_row + nt * 2048 + bc);
            #pragma unroll
            for (int mt = 0; mt < 2; mt++)
                #pragma unroll
                for (int nb = 0; nb < 8; nb++)
                    mma16816_bf(c[mt][nb], aqh[mt], &bk[nb >> 1][(nb & 1) * 2]);
        }
    }

    // ---- epilogue: exp in-place, per-row partial sums, store e ----
    float rs[2][2];
    #pragma unroll
    for (int mt = 0; mt < 2; mt++) {
        float s01 = 0.0f, s23 = 0.0f;
        #pragma unroll
        for (int nb = 0; nb < 8; nb++) {
            c[mt][nb][0] = __expf(c[mt][nb][0]);
            c[mt][nb][1] = __expf(c[mt][nb][1]);
            c[mt][nb][2] = __expf(c[mt][nb][2]);
            c[mt][nb][3] = __expf(c[mt][nb][3]);
            s01 += c[mt][nb][0] + c[mt][nb][1];
            s23 += c[mt][nb][2] + c[mt][nb][3];
        }
        rs[mt][0] = s01;
        rs[mt][1] = s23;
    }
    #pragma unroll
    for (int mt = 0; mt < 2; mt++)
        #pragma unroll
        for (int h = 0; h < 2; h++) {
            float v = rs[mt][h];
            v += __shfl_xor_sync(0xffffffffu, v, 1);
            v += __shfl_xor_sync(0xffffffffu, v, 2);
            rs[mt][h] = v;
        }

    __syncthreads();
    float* ps = (float*)smem;
    const int g = lane >> 2, t = lane & 3;
    if (t == 0) {
        const int slot = (wid & 3) * 128;
        #pragma unroll
        for (int mt = 0; mt < 2; mt++) {
            ps[slot + wm + mt * 16 + g]     = rs[mt][0];
            ps[slot + wm + mt * 16 + g + 8] = rs[mt][1];
        }
    }
    __syncthreads();
    if (tid < 128) {
        float tot = ps[tid] + ps[128 + tid] + ps[256 + tid] + ps[384 + tid];
        g_rowpart[((size_t)(b * SEQ + bm + tid)) * 8 + blockIdx.x] = tot;
    }

    #pragma unroll
    for (int mt = 0; mt < 2; mt++) {
        const size_t r0 = (size_t)b * SEQ + bm + wm + mt * 16 + g;
        #pragma unroll
        for (int nb = 0; nb < 8; nb++) {
            const int col = bn + wn + nb * 8 + 2 * t;
            *(float2*)&P[r0 * SEQ + col]       = make_float2(c[mt][nb][0], c[mt][nb][1]);
            *(float2*)&P[(r0 + 8) * SEQ + col] = make_float2(c[mt][nb][2], c[mt][nb][3]);
        }
    }
}

// ---------------------------------------------------------------------------
// K2: row-sum inverse
// ---------------------------------------------------------------------------
__global__ __launch_bounds__(256) void inv_kernel() {
    const int r = blockIdx.x * 256 + threadIdx.x;
    if (r >= BATCH * SEQ) return;
    const float4* p = (const float4*)(g_rowpart + (size_t)r * 8);
    float4 a = p[0], bq = p[1];
    g_inv[r] = 1.0f / (a.x + a.y + a.z + a.w + bq.x + bq.y + bq.z + bq.w);
}

// ---------------------------------------------------------------------------
// K3: O = P @ V (2-pass fp16) + normalization + P writeback.
// P read DIRECTLY into registers (no smem staging), prefetched 1 chunk ahead;
// V triple-buffered cp.async, 2 chunks ahead.  smem 80 KB -> 2 CTAs/SM.
// ---------------------------------------------------------------------------
#define AV_AH 0
#define AV_AL 16384
#define AV_V  32768          // 3 stages x 16384
#define AV_BYTES 81920

__global__ __launch_bounds__(256, 2) void av_mma_kernel(float* __restrict__ P,
                                                        float* __restrict__ O) {
    extern __shared__ char smem[];
    const uint32_t sb = smem_u32(smem);
    const int tid  = threadIdx.x;
    const int lane = tid & 31;
    const int wid  = tid >> 5;
    const int bm = blockIdx.x * 128;
    const int b  = blockIdx.y;
    const int wm = (wid >> 1) * 32;
    const int wn = (wid & 1) * 64;

    float c[2][8][4];
    #pragma unroll
    for (int i = 0; i < 2; i++)
        #pragma unroll
        for (int j = 0; j < 8; j++)
            #pragma unroll
            for (int q = 0; q < 4; q++) c[i][j][q] = 0.0f;

    const int lr  = tid >> 1;
    const int lc0 = (tid & 1) * 4;
    const int lsw = lr & 7;
    float* prow = P + ((size_t)b * SEQ + bm + lr) * SEQ + (tid & 1) * 32;
    const size_t vbase = ((size_t)b * DIM + lr) * SEQ;
    const float inv_r = g_inv[b * SEQ + bm + lr];
    const float fs    = inv_r * PSCALE;

    const int s7 = lane & 7;
    const uint32_t a_row = (uint32_t)(wm + (lane & 15)) * 128;
    const int a_k = (lane >> 4) & 1;
    const uint32_t b_row = (uint32_t)(wn + (lane & 7) + ((lane >> 4) << 3)) * 128;
    const int b_k = (lane >> 3) & 1;

    // ---- prologue: P chunk 0 -> regs; V chunks 0,1 -> smem stages 0,1 ----
    float4 x[8];
    #pragma unroll
    for (int i = 0; i < 8; i++) x[i] = *(const float4*)(prow + i * 4);
    #pragma unroll
    for (int s = 0; s < 2; s++) {
        #pragma unroll
        for (int j = 0; j < 4; j++) {
            const int ch = lc0 + j;
            CP_ASYNC16(sb + AV_V + s * 16384 + lr * 128 + (uint32_t)((ch ^ lsw) << 4),
                       g_vh + vbase + s * 64 + ch * 8);
        }
        CP_COMMIT();
    }

    for (int kc = 0; kc < 32; kc++) {
        const int kk = kc * 64;
        const uint32_t vcur = sb + AV_V + (uint32_t)(kc % 3) * 16384;

        // ---- normalize x -> p writeback; split p*2^14 -> A hi/lo smem ----
        #pragma unroll
        for (int j = 0; j < 4; j++) {
            float4 x0 = x[2 * j], x1 = x[2 * j + 1];
            *(float4*)(prow + kk + 8 * j) =
                make_float4(x0.x * inv_r, x0.y * inv_r, x0.z * inv_r, x0.w * inv_r);
            *(float4*)(prow + kk + 8 * j + 4) =
                make_float4(x1.x * inv_r, x1.y * inv_r, x1.z * inv_r, x1.w * inv_r);
            uint4 hv, lv;
            split2h(x0.x * fs, x0.y * fs, hv.x, lv.x);
            split2h(x0.z * fs, x0.w * fs, hv.y, lv.y);
            split2h(x1.x * fs, x1.y * fs, hv.z, lv.z);
            split2h(x1.z * fs, x1.w * fs, hv.w, lv.w);
            const uint32_t doff = lr * 128 + (uint32_t)(((lc0 + j) ^ lsw) << 4);
            *(uint4*)(smem + AV_AH + doff) = hv;
            *(uint4*)(smem + AV_AL + doff) = lv;
        }

        // ---- prefetch next P chunk into regs (latency hides under MMA) ----
        {
            const int kn = (kc < 31) ? kk + 64 : kk;
            #pragma unroll
            for (int i = 0; i < 8; i++) x[i] = *(const float4*)(prow + kn + i * 4);
        }

        // ---- V prefetch 2 ahead; wait for V chunk kc ----
        if (kc < 30) {
            const int kv = (kc + 2) * 64;
            const uint32_t vdst = sb + AV_V + (uint32_t)((kc + 2) % 3) * 16384;
            #pragma unroll
            for (int j = 0; j < 4; j++) {
                const int ch = lc0 + j;
                CP_ASYNC16(vdst + lr * 128 + (uint32_t)((ch ^ lsw) << 4),
                           g_vh + vbase + kv + ch * 8);
            }
            CP_COMMIT();
            CP_WAIT2();
        } else if (kc == 30) {
            CP_WAIT1();
        } else {
            CP_WAIT0();
        }
        __syncthreads();

        // ---- MMA: hi pass then lo pass, A-frag regs reused ----
        #pragma unroll
        for (int ks = 0; ks < 4; ks++) {
            uint32_t bf[4][4], af[2][4];
            const uint32_t bc = (uint32_t)(((2 * ks + b_k) ^ s7) << 4);
            #pragma unroll
            for (int nt = 0; nt < 4; nt++)
                ldmx4(bf[nt], vcur + b_row + nt * 2048 + bc);
            const uint32_t ac = (uint32_t)(((2 * ks + a_k) ^ s7) << 4);
            ldmx4(af[0], sb + AV_AH + a_row + ac);
            ldmx4(af[1], sb + AV_AH + a_row + 2048 + ac);
            #pragma unroll
            for (int mt = 0; mt < 2; mt++)
                #pragma unroll
                for (int nb = 0; nb < 8; nb++)
                    mma16816_fp(c[mt][nb], af[mt], &bf[nb >> 1][(nb & 1) * 2]);
            ldmx4(af[0], sb + AV_AL + a_row + ac);
            ldmx4(af[1], sb + AV_AL + a_row + 2048 + ac);
            #pragma unroll
            for (int mt = 0; mt < 2; mt++)
                #pragma unroll
                for (int nb = 0; nb < 8; nb++)
                    mma16816_fp(c[mt][nb], af[mt], &bf[nb >> 1][(nb & 1) * 2]);
        }
        __syncthreads();
    }

    const int g = lane >> 2, t = lane & 3;
    #pragma unroll
    for (int mt = 0; mt < 2; mt++) {
        const size_t r0 = (size_t)b * SEQ + bm + wm + mt * 16 + g;
        #pragma unroll
        for (int nb = 0; nb < 8; nb++) {
            const int col = wn + nb * 8 + 2 * t;
            *(float2*)&O[r0 * DIM + col] =
                make_float2(c[mt][nb][0] * PSCALE_I, c[mt][nb][1] * PSCALE_I);
            *(float2*)&O[(r0 + 8) * DIM + col] =
                make_float2(c[mt][nb][2] * PSCALE_I, c[mt][nb][3] * PSCALE_I);
        }
    }
}

// ---------------------------------------------------------------------------
// Launch: out = [ output (B*N*D) | attn (B*N*N) ]
// ---------------------------------------------------------------------------
extern "C" void kernel_launch(void* const* d_in, const int* in_sizes, int n_in,
                              void* d_out, int out_size) {
    const float* q = (const float*)d_in[0];
    const float* k = (const float*)d_in[1];
    const float* v = (const float*)d_in[2];
    float* out  = (float*)d_out;
    float* attn = out + (size_t)BATCH * SEQ * DIM;

    cudaFuncSetAttribute(scores_mma_kernel,
                         cudaFuncAttributeMaxDynamicSharedMemorySize, SC_BYTES);
    cudaFuncSetAttribute(av_mma_kernel,
                         cudaFuncAttributeMaxDynamicSharedMemorySize, AV_BYTES);

    const int n4 = BATCH * SEQ * DIM / 4;
    split_kernel<0><<<(n4 + 255) / 256, 256>>>(q, n4);
    split_kernel<1><<<(n4 + 255) / 256, 256>>>(k, n4);

    dim3 gv(SEQ / 32, DIM / 32, BATCH);
    vtrans_kernel<<<gv, 256>>>(v);

    dim3 g1(SEQ / 256, SEQ / 128, BATCH);   // 8 x 16 x 16 = 2048 CTAs
    scores_mma_kernel<<<g1, 512, SC_BYTES>>>(attn);

    inv_kernel<<<(BATCH * SEQ) / 256, 256>>>();

    dim3 g3(SEQ / 128, BATCH);
    av_mma_kernel<<<g3, 256, AV_BYTES>>>(attn, out);
}